// round 1
// baseline (speedup 1.0000x reference)
#include <cuda_runtime.h>
#include <cstdint>
#include <cstddef>

// ---------------------------------------------------------------------------
// FastMLayer: rmsnorm -> GEMM1 -> GEMM2 -> mask -> expm(Taylor,16x16 nilpotent)
//             -> GEMM3
// All GEMMs via mma.sync m16n8k8 tf32 (fp32 accum). Scratch in __device__
// globals (no allocation). Every launch is a plain kernel launch on the
// capture stream.
// ---------------------------------------------------------------------------

#define K_ROWS   8192
#define K_INDIM  4096
#define K_EMB    1024
#define K_NN     16
#define K_MM     256
#define K_OUTDIM 4096
#define RMS_EPS  1.1920928955078125e-07f

__device__ float g_scale[K_ROWS];
__device__ float g_latent[K_ROWS * (size_t)K_EMB];
__device__ float g_flatm[K_ROWS * (size_t)K_MM];
__device__ float g_flatexp[K_ROWS * (size_t)K_MM];

// ---------------------------------------------------------------------------
// helpers
// ---------------------------------------------------------------------------
__device__ __forceinline__ uint32_t f2tf32(float f) {
    uint32_t u;
    asm("cvt.rna.tf32.f32 %0, %1;" : "=r"(u) : "f"(f));
    return u;
}

__device__ __forceinline__ void mma_tf32(float* c, const uint32_t* a, const uint32_t* b) {
    asm volatile(
        "mma.sync.aligned.m16n8k8.row.col.f32.tf32.tf32.f32 "
        "{%0,%1,%2,%3}, {%4,%5,%6,%7}, {%8,%9}, {%0,%1,%2,%3};\n"
        : "+f"(c[0]), "+f"(c[1]), "+f"(c[2]), "+f"(c[3])
        : "r"(a[0]), "r"(a[1]), "r"(a[2]), "r"(a[3]),
          "r"(b[0]), "r"(b[1]));
}

// ---------------------------------------------------------------------------
// Kernel 1: per-row RMS scale = rsqrt(mean(x^2) + eps)
// ---------------------------------------------------------------------------
__global__ void __launch_bounds__(256) rms_kernel(const float* __restrict__ x) {
    int row = blockIdx.x;
    const float4* xr = reinterpret_cast<const float4*>(x + (size_t)row * K_INDIM);
    float s = 0.f;
    for (int i = threadIdx.x; i < K_INDIM / 4; i += 256) {
        float4 v = xr[i];
        s += v.x * v.x + v.y * v.y + v.z * v.z + v.w * v.w;
    }
#pragma unroll
    for (int o = 16; o; o >>= 1) s += __shfl_xor_sync(0xFFFFFFFFu, s, o);
    __shared__ float ws[8];
    if ((threadIdx.x & 31) == 0) ws[threadIdx.x >> 5] = s;
    __syncthreads();
    if (threadIdx.x == 0) {
        float t = 0.f;
#pragma unroll
        for (int i = 0; i < 8; i++) t += ws[i];
        g_scale[row] = rsqrtf(t * (1.0f / K_INDIM) + RMS_EPS);
    }
}

// ---------------------------------------------------------------------------
// Generic tf32 GEMM, 128x128 block tile, 32 K-tile, 8 warps (4x2), warp tile
// 32x64 (2x8 m16n8k8 fragments). C = A@B + bias, optional A row-scale
// (MODE 0) and strictly-upper-triangular mask epilogue (MODE 1).
//   MODE 0: A = x (scaled by g_scale), C = g_latent
//   MODE 1: A = g_latent,              C = g_flatm  (masked)
//   MODE 2: A = g_flatexp,             C = Cout (d_out)
// ---------------------------------------------------------------------------
template <int MODE>
__global__ void __launch_bounds__(256) gemm_tf32(
    const float* __restrict__ Ain, const float* __restrict__ B,
    const float* __restrict__ bias, float* __restrict__ Cout,
    int M, int N, int K)
{
    constexpr bool SCALE_A = (MODE == 0);
    constexpr bool MASK    = (MODE == 1);

    const float* __restrict__ A =
        (MODE == 1) ? g_latent : (MODE == 2) ? g_flatexp : Ain;
    float* __restrict__ C =
        (MODE == 0) ? g_latent : (MODE == 1) ? g_flatm : Cout;

    __shared__ uint32_t As[128][36];   // [m][k], stride 36 (16B aligned rows)
    __shared__ uint32_t Bs[32][132];   // [k][n]

    const int bm = blockIdx.x * 128;
    const int bn = blockIdx.y * 128;
    const int tid = threadIdx.x;
    const int warp = tid >> 5, lane = tid & 31;
    const int wm = (warp >> 1) * 32;   // 4 warps along M
    const int wn = (warp & 1) * 64;    // 2 warps along N
    const int g = lane >> 2, t = lane & 3;

    float acc[2][8][4];
#pragma unroll
    for (int i = 0; i < 2; i++)
#pragma unroll
        for (int j = 0; j < 8; j++)
#pragma unroll
            for (int r = 0; r < 4; r++) acc[i][j][r] = 0.f;

    for (int k0 = 0; k0 < K; k0 += 32) {
        // --- load A tile 128x32 (scaled, tf32) ---
#pragma unroll
        for (int it = 0; it < 4; it++) {
            int v = tid + it * 256;
            int r = v >> 3;           // 8 float4 per row
            int c4 = v & 7;
            float4 src = *reinterpret_cast<const float4*>(
                A + (size_t)(bm + r) * K + k0 + c4 * 4);
            float sc = SCALE_A ? g_scale[bm + r] : 1.0f;
            uint32_t* dst = &As[r][c4 * 4];
            dst[0] = f2tf32(src.x * sc);
            dst[1] = f2tf32(src.y * sc);
            dst[2] = f2tf32(src.z * sc);
            dst[3] = f2tf32(src.w * sc);
        }
        // --- load B tile 32x128 (tf32) ---
#pragma unroll
        for (int it = 0; it < 4; it++) {
            int v = tid + it * 256;
            int r = v >> 5;           // 32 float4 per row
            int c4 = v & 31;
            float4 src = *reinterpret_cast<const float4*>(
                B + (size_t)(k0 + r) * N + bn + c4 * 4);
            uint32_t* dst = &Bs[r][c4 * 4];
            dst[0] = f2tf32(src.x);
            dst[1] = f2tf32(src.y);
            dst[2] = f2tf32(src.z);
            dst[3] = f2tf32(src.w);
        }
        __syncthreads();

#pragma unroll
        for (int kk = 0; kk < 32; kk += 8) {
            uint32_t a[2][4], b[8][2];
#pragma unroll
            for (int i = 0; i < 2; i++) {
                int m = wm + i * 16;
                a[i][0] = As[m + g][kk + t];
                a[i][1] = As[m + g + 8][kk + t];
                a[i][2] = As[m + g][kk + t + 4];
                a[i][3] = As[m + g + 8][kk + t + 4];
            }
#pragma unroll
            for (int j = 0; j < 8; j++) {
                int n = wn + j * 8;
                b[j][0] = Bs[kk + t][n + g];
                b[j][1] = Bs[kk + t + 4][n + g];
            }
#pragma unroll
            for (int i = 0; i < 2; i++)
#pragma unroll
                for (int j = 0; j < 8; j++) mma_tf32(acc[i][j], a[i], b[j]);
        }
        __syncthreads();
    }

    // --- epilogue: bias (+ mask), store float2 ---
#pragma unroll
    for (int i = 0; i < 2; i++) {
#pragma unroll
        for (int j = 0; j < 8; j++) {
            int n0 = bn + wn + j * 8 + 2 * t;
            float bv0 = bias[n0], bv1 = bias[n0 + 1];
            float v00 = acc[i][j][0] + bv0;
            float v01 = acc[i][j][1] + bv1;
            float v10 = acc[i][j][2] + bv0;
            float v11 = acc[i][j][3] + bv1;
            if (MASK) {
                // keep only strictly-upper of the 16x16 (col > row of flat idx)
                if (!((n0 & 15) > (n0 >> 4)))       { v00 = 0.f; v10 = 0.f; }
                if (!(((n0 + 1) & 15) > ((n0 + 1) >> 4))) { v01 = 0.f; v11 = 0.f; }
            }
            int m0 = bm + wm + i * 16 + g;
            *reinterpret_cast<float2*>(&C[(size_t)m0 * N + n0]) =
                make_float2(v00, v01);
            *reinterpret_cast<float2*>(&C[(size_t)(m0 + 8) * N + n0]) =
                make_float2(v10, v11);
        }
    }
}

// ---------------------------------------------------------------------------
// Kernel 4: expm of strictly-upper 16x16 via Taylor (exact: M^16 = 0).
// One block (256 threads) per row; thread (i,j) owns one element.
// term_k[i][j] == 0 whenever j - i < k, so skip those products.
// ---------------------------------------------------------------------------
__global__ void __launch_bounds__(256) expm_kernel() {
    int row = blockIdx.x;
    int idx = threadIdx.x;
    int i = idx >> 4, j = idx & 15;

    __shared__ float Msm[256];
    __shared__ float Ts[256];

    float m = g_flatm[(size_t)row * K_MM + idx];
    Msm[idx] = m;
    Ts[idx] = m;                       // term after k=1
    float res = ((i == j) ? 1.0f : 0.0f) + m;
    __syncthreads();

#pragma unroll
    for (int k = 2; k <= 15; k++) {
        float s = 0.f;
        if (j - i >= k) {
#pragma unroll
            for (int l = 0; l < 16; l++) s += Ts[i * 16 + l] * Msm[l * 16 + j];
            s /= (float)k;
        }
        __syncthreads();
        Ts[idx] = s;
        res += s;
        __syncthreads();
    }
    g_flatexp[(size_t)row * K_MM + idx] = res;
}

// ---------------------------------------------------------------------------
// launch
// ---------------------------------------------------------------------------
extern "C" void kernel_launch(void* const* d_in, const int* in_sizes, int n_in,
                              void* d_out, int out_size) {
    (void)in_sizes; (void)n_in; (void)out_size;
    const float* x   = (const float*)d_in[0];
    const float* W_u = (const float*)d_in[1];
    const float* b_u = (const float*)d_in[2];
    const float* W_t = (const float*)d_in[3];
    const float* b_t = (const float*)d_in[4];
    const float* W_s = (const float*)d_in[5];
    const float* b_s = (const float*)d_in[6];
    float* out = (float*)d_out;

    rms_kernel<<<K_ROWS, 256>>>(x);

    // GEMM1: latent = (x * scale) @ W_u + b_u    [8192 x 1024]
    gemm_tf32<0><<<dim3(K_ROWS / 128, K_EMB / 128), 256>>>(
        x, W_u, b_u, nullptr, K_ROWS, K_EMB, K_INDIM);

    // GEMM2: flat_m = latent @ W_t + b_t, masked  [8192 x 256]
    gemm_tf32<1><<<dim3(K_ROWS / 128, K_MM / 128), 256>>>(
        nullptr, W_t, b_t, nullptr, K_ROWS, K_MM, K_EMB);

    // expm per row
    expm_kernel<<<K_ROWS, 256>>>();

    // GEMM3: out = flat_exp @ W_s + b_s           [8192 x 4096]
    gemm_tf32<2><<<dim3(K_ROWS / 128, K_OUTDIM / 128), 256>>>(
        nullptr, W_s, b_s, out, K_ROWS, K_OUTDIM, K_MM);
}

// round 3
// speedup vs baseline: 1.6143x; 1.6143x over previous
#include <cuda_runtime.h>
#include <cstdint>
#include <cstddef>

#define K_ROWS   8192
#define K_INDIM  4096
#define K_EMB    1024
#define K_MM     256
#define K_PACK   128      // packed strictly-upper dim (120 used, padded)
#define K_OUTDIM 4096
#define RMS_EPS  1.1920928955078125e-07f

// ---------------- scratch (device globals; no allocation) -------------------
__device__ float g_xr[(size_t)K_ROWS * K_INDIM];     // rms-scaled, rna-tf32 x
__device__ float g_Wu[(size_t)K_INDIM * K_EMB];      // rounded W_u  [K][N]
__device__ float g_Wt[(size_t)K_EMB * K_MM];         // rounded W_t  [K][N]
__device__ float g_latent[(size_t)K_ROWS * K_EMB];
__device__ float g_flatm[(size_t)K_ROWS * K_MM];
__device__ float g_fexpP[(size_t)K_ROWS * K_PACK];   // packed strictly-upper expm
__device__ float g_WsP[(size_t)K_PACK * K_OUTDIM];   // packed rounded W_s rows
__device__ float g_bias2[K_OUTDIM];                  // b_s + sum(diag rows of W_s)

// ---------------- helpers ---------------------------------------------------
__device__ __forceinline__ uint32_t f2tf32(float f) {
    uint32_t u; asm("cvt.rna.tf32.f32 %0, %1;" : "=r"(u) : "f"(f)); return u;
}
__device__ __forceinline__ float roundtf(float f) { return __uint_as_float(f2tf32(f)); }

__device__ __forceinline__ void cpa16(void* sdst, const void* g) {
    uint32_t s = (uint32_t)__cvta_generic_to_shared(sdst);
    asm volatile("cp.async.cg.shared.global [%0], [%1], 16;\n" :: "r"(s), "l"(g));
}

__device__ __forceinline__ void mma_tf32(float* c, const uint32_t* a, const uint32_t* b) {
    asm volatile(
        "mma.sync.aligned.m16n8k8.row.col.f32.tf32.tf32.f32 "
        "{%0,%1,%2,%3}, {%4,%5,%6,%7}, {%8,%9}, {%0,%1,%2,%3};\n"
        : "+f"(c[0]), "+f"(c[1]), "+f"(c[2]), "+f"(c[3])
        : "r"(a[0]), "r"(a[1]), "r"(a[2]), "r"(a[3]),
          "r"(b[0]), "r"(b[1]));
}

// ---------------------------------------------------------------------------
// rms: scale row by rsqrt(mean(x^2)+eps), write rna-tf32 rounded copy
// ---------------------------------------------------------------------------
__global__ void __launch_bounds__(256) rms_kernel(const float* __restrict__ x) {
    int row = blockIdx.x;
    const float4* xr = reinterpret_cast<const float4*>(x + (size_t)row * K_INDIM);
    float s = 0.f;
#pragma unroll 4
    for (int i = threadIdx.x; i < K_INDIM / 4; i += 256) {
        float4 v = xr[i];
        s += v.x * v.x + v.y * v.y + v.z * v.z + v.w * v.w;
    }
#pragma unroll
    for (int o = 16; o; o >>= 1) s += __shfl_xor_sync(0xFFFFFFFFu, s, o);
    __shared__ float ws[8];
    __shared__ float ssc;
    if ((threadIdx.x & 31) == 0) ws[threadIdx.x >> 5] = s;
    __syncthreads();
    if (threadIdx.x == 0) {
        float t = 0.f;
#pragma unroll
        for (int i = 0; i < 8; i++) t += ws[i];
        ssc = rsqrtf(t * (1.0f / K_INDIM) + RMS_EPS);
    }
    __syncthreads();
    float sc = ssc;
    float4* out = reinterpret_cast<float4*>(g_xr + (size_t)row * K_INDIM);
#pragma unroll 4
    for (int i = threadIdx.x; i < K_INDIM / 4; i += 256) {
        float4 v = xr[i];
        out[i] = make_float4(roundtf(v.x * sc), roundtf(v.y * sc),
                             roundtf(v.z * sc), roundtf(v.w * sc));
    }
}

// ---------------------------------------------------------------------------
// rounded weight copies.  SEL 0 -> g_Wu, 1 -> g_Wt
// ---------------------------------------------------------------------------
template <int SEL>
__global__ void __launch_bounds__(256) round_copy(const float* __restrict__ in, int n4) {
    float* out = (SEL == 0) ? g_Wu : g_Wt;
    int i = blockIdx.x * 256 + threadIdx.x;
    if (i < n4) {
        float4 v = reinterpret_cast<const float4*>(in)[i];
        reinterpret_cast<float4*>(out)[i] =
            make_float4(roundtf(v.x), roundtf(v.y), roundtf(v.z), roundtf(v.w));
    }
}

// ---------------------------------------------------------------------------
// pack W_s: rows for the 120 strictly-upper positions (rounded), rows 120-127
// zero, and g_bias2 = b_s + sum of the 16 diagonal rows.
// ---------------------------------------------------------------------------
__global__ void __launch_bounds__(256) pack_ws(const float* __restrict__ Ws,
                                               const float* __restrict__ bs) {
    int q = blockIdx.x;   // 0..128
    if (q < 120) {
        int i = 0, rem = q;
        while (rem >= 15 - i) { rem -= 15 - i; i++; }
        int p = i * 16 + (i + 1 + rem);
        for (int n = threadIdx.x; n < K_OUTDIM; n += 256)
            g_WsP[(size_t)q * K_OUTDIM + n] = roundtf(Ws[(size_t)p * K_OUTDIM + n]);
    } else if (q < 128) {
        for (int n = threadIdx.x; n < K_OUTDIM; n += 256)
            g_WsP[(size_t)q * K_OUTDIM + n] = 0.f;
    } else {
        for (int n = threadIdx.x; n < K_OUTDIM; n += 256) {
            float s = bs[n];
#pragma unroll
            for (int d = 0; d < 16; d++) s += Ws[(size_t)(17 * d) * K_OUTDIM + n];
            g_bias2[n] = s;
        }
    }
}

// ---------------------------------------------------------------------------
// tf32 mma.sync GEMM, 128x128 CTA tile, K-tile 32, 3-stage cp.async pipeline.
// 8 warps (4x2), warp tile 32x64 (2x8 m16n8k8).
// MODE 0: g_xr    @ g_Wu  + b_u   -> g_latent (rna-rounded epilogue)
// MODE 1: g_latent@ g_Wt  + b_t   -> g_flatm  (strict-upper mask)
// MODE 2: g_fexpP @ g_WsP + bias2 -> Cout
// ---------------------------------------------------------------------------
#define A_STRIDE 36
#define B_STRIDE 132
#define A_ST_FLOATS (128 * A_STRIDE)      // 4608
#define B_ST_FLOATS (32 * B_STRIDE)       // 4224
#define SMEM_GEMM ((3 * (A_ST_FLOATS + B_ST_FLOATS)) * 4)   // 105984 B

template <int MODE>
__global__ void __launch_bounds__(256, 1) gemm_mma(const float* __restrict__ BiasIn,
                                                   float* __restrict__ Cout) {
    constexpr int KDIM = (MODE == 0) ? K_INDIM : (MODE == 1) ? K_EMB : K_PACK;
    constexpr int NDIM = (MODE == 0) ? K_EMB : (MODE == 1) ? K_MM : K_OUTDIM;
    constexpr int KT = KDIM / 32;

    const float* __restrict__ A =
        (MODE == 0) ? g_xr : (MODE == 1) ? g_latent : g_fexpP;
    const float* __restrict__ B =
        (MODE == 0) ? g_Wu : (MODE == 1) ? g_Wt : g_WsP;
    float* __restrict__ C =
        (MODE == 0) ? g_latent : (MODE == 1) ? g_flatm : Cout;
    const float* __restrict__ bias = (MODE == 2) ? g_bias2 : BiasIn;

    extern __shared__ float sm[];
    float* AsBase = sm;
    float* BsBase = sm + 3 * A_ST_FLOATS;

    const int tid = threadIdx.x, warp = tid >> 5, lane = tid & 31;
    const int bn = blockIdx.x * 128, bm = blockIdx.y * 128;
    const int wm = (warp >> 1) * 32, wn = (warp & 1) * 64;
    const int g = lane >> 2, t = lane & 3;

    float acc[2][8][4];
#pragma unroll
    for (int i = 0; i < 2; i++)
#pragma unroll
        for (int j = 0; j < 8; j++)
#pragma unroll
            for (int r = 0; r < 4; r++) acc[i][j][r] = 0.f;

    auto load_tile = [&](int kt, int st) {
        float* a = AsBase + st * A_ST_FLOATS;
        float* b = BsBase + st * B_ST_FLOATS;
#pragma unroll
        for (int i = 0; i < 4; i++) {           // A: 128 x 32
            int v = tid + i * 256, r = v >> 3, c = v & 7;
            cpa16(a + r * A_STRIDE + c * 4,
                  A + (size_t)(bm + r) * KDIM + kt * 32 + c * 4);
        }
#pragma unroll
        for (int i = 0; i < 4; i++) {           // B: 32 x 128
            int v = tid + i * 256, r = v >> 5, c = v & 31;
            cpa16(b + r * B_STRIDE + c * 4,
                  B + (size_t)(kt * 32 + r) * NDIM + bn + c * 4);
        }
        asm volatile("cp.async.commit_group;\n" ::: "memory");
    };

    auto compute = [&](int st) {
        const uint32_t* au = reinterpret_cast<const uint32_t*>(AsBase + st * A_ST_FLOATS);
        const uint32_t* bu = reinterpret_cast<const uint32_t*>(BsBase + st * B_ST_FLOATS);
#pragma unroll
        for (int kk = 0; kk < 32; kk += 8) {
            uint32_t a[2][4], b[8][2];
#pragma unroll
            for (int i = 0; i < 2; i++) {
                int m = wm + i * 16;
                a[i][0] = au[(m + g) * A_STRIDE + kk + t];
                a[i][1] = au[(m + g + 8) * A_STRIDE + kk + t];
                a[i][2] = au[(m + g) * A_STRIDE + kk + t + 4];
                a[i][3] = au[(m + g + 8) * A_STRIDE + kk + t + 4];
            }
#pragma unroll
            for (int j = 0; j < 8; j++) {
                int n = wn + j * 8;
                b[j][0] = bu[(kk + t) * B_STRIDE + n + g];
                b[j][1] = bu[(kk + t + 4) * B_STRIDE + n + g];
            }
#pragma unroll
            for (int i = 0; i < 2; i++)
#pragma unroll
                for (int j = 0; j < 8; j++) mma_tf32(acc[i][j], a[i], b[j]);
        }
    };

    load_tile(0, 0);
    load_tile(1, 1);

    for (int kt = 0; kt < KT; kt++) {
        if (kt < KT - 1) asm volatile("cp.async.wait_group 1;\n" ::: "memory");
        else             asm volatile("cp.async.wait_group 0;\n" ::: "memory");
        __syncthreads();
        if (kt + 2 < KT) load_tile(kt + 2, (kt + 2) % 3);
        compute(kt % 3);
    }

    // epilogue
#pragma unroll
    for (int i = 0; i < 2; i++) {
#pragma unroll
        for (int j = 0; j < 8; j++) {
            int n0 = bn + wn + j * 8 + 2 * t;
            float bv0 = bias[n0], bv1 = bias[n0 + 1];
            float v00 = acc[i][j][0] + bv0;
            float v01 = acc[i][j][1] + bv1;
            float v10 = acc[i][j][2] + bv0;
            float v11 = acc[i][j][3] + bv1;
            if (MODE == 1) {
                if (!((n0 & 15) > (n0 >> 4)))             { v00 = 0.f; v10 = 0.f; }
                if (!(((n0 + 1) & 15) > ((n0 + 1) >> 4))) { v01 = 0.f; v11 = 0.f; }
            }
            if (MODE == 0) {
                v00 = roundtf(v00); v01 = roundtf(v01);
                v10 = roundtf(v10); v11 = roundtf(v11);
            }
            int m0 = bm + wm + i * 16 + g;
            *reinterpret_cast<float2*>(&C[(size_t)m0 * NDIM + n0]) = make_float2(v00, v01);
            *reinterpret_cast<float2*>(&C[(size_t)(m0 + 8) * NDIM + n0]) = make_float2(v10, v11);
        }
    }
}

// ---------------------------------------------------------------------------
// expm of strictly-upper 16x16 via Taylor (exact: M^16 = 0).
// Writes PACKED strictly-upper output (rna-rounded), cols 120..127 zero.
// ---------------------------------------------------------------------------
__global__ void __launch_bounds__(256) expm_kernel() {
    int row = blockIdx.x;
    int idx = threadIdx.x;
    int i = idx >> 4, j = idx & 15;

    __shared__ float Msm[256];
    __shared__ float Ts[256];

    float m = g_flatm[(size_t)row * K_MM + idx];
    Msm[idx] = m;
    Ts[idx] = m;
    float res = ((i == j) ? 1.0f : 0.0f) + m;
    __syncthreads();

#pragma unroll
    for (int k = 2; k <= 15; k++) {
        float s = 0.f;
        if (j - i >= k) {
#pragma unroll
            for (int l = 0; l < 16; l++) s += Ts[i * 16 + l] * Msm[l * 16 + j];
            s /= (float)k;
        }
        __syncthreads();
        Ts[idx] = s;
        res += s;
        __syncthreads();
    }
    if (j > i) {
        int q = i * 15 - (i * (i - 1)) / 2 + (j - i - 1);
        g_fexpP[(size_t)row * K_PACK + q] = roundtf(res);
    }
    if (idx < 8) g_fexpP[(size_t)row * K_PACK + 120 + idx] = 0.f;
}

// ---------------------------------------------------------------------------
// launch
// ---------------------------------------------------------------------------
extern "C" void kernel_launch(void* const* d_in, const int* in_sizes, int n_in,
                              void* d_out, int out_size) {
    (void)in_sizes; (void)n_in; (void)out_size;
    const float* x   = (const float*)d_in[0];
    const float* W_u = (const float*)d_in[1];
    const float* b_u = (const float*)d_in[2];
    const float* W_t = (const float*)d_in[3];
    const float* b_t = (const float*)d_in[4];
    const float* W_s = (const float*)d_in[5];
    const float* b_s = (const float*)d_in[6];
    float* out = (float*)d_out;

    cudaFuncSetAttribute(gemm_mma<0>, cudaFuncAttributeMaxDynamicSharedMemorySize, SMEM_GEMM);
    cudaFuncSetAttribute(gemm_mma<1>, cudaFuncAttributeMaxDynamicSharedMemorySize, SMEM_GEMM);
    cudaFuncSetAttribute(gemm_mma<2>, cudaFuncAttributeMaxDynamicSharedMemorySize, SMEM_GEMM);

    rms_kernel<<<K_ROWS, 256>>>(x);
    round_copy<0><<<(K_INDIM * K_EMB / 4) / 256, 256>>>(W_u, K_INDIM * K_EMB / 4);
    round_copy<1><<<(K_EMB * K_MM / 4) / 256, 256>>>(W_t, K_EMB * K_MM / 4);
    pack_ws<<<129, 256>>>(W_s, b_s);

    // GEMM1: latent = xr @ Wu + b_u           [8192 x 1024], K=4096
    gemm_mma<0><<<dim3(K_EMB / 128, K_ROWS / 128), 256, SMEM_GEMM>>>(b_u, nullptr);

    // GEMM2: flatm = latent @ Wt + b_t, mask  [8192 x 256], K=1024
    gemm_mma<1><<<dim3(K_MM / 128, K_ROWS / 128), 256, SMEM_GEMM>>>(b_t, nullptr);

    // expm -> packed
    expm_kernel<<<K_ROWS, 256>>>();

    // GEMM3: out = fexpP @ WsP + bias2        [8192 x 4096], K=128
    gemm_mma<2><<<dim3(K_OUTDIM / 128, K_ROWS / 128), 256, SMEM_GEMM>>>(nullptr, out);
}

// round 4
// speedup vs baseline: 3.9550x; 2.4500x over previous
#include <cuda_runtime.h>
#include <cuda_fp16.h>
#include <cstdint>
#include <cstddef>

#define K_ROWS   8192
#define K_INDIM  4096
#define K_EMB    1024
#define K_MM     256
#define K_PACK   128
#define K_OUTDIM 4096
#define RMS_EPS  1.1920928955078125e-07f

// ---------------- scratch (device globals; no allocation) -------------------
__device__ __half g_xh[(size_t)K_ROWS * K_INDIM];     // rms-scaled x, fp16
__device__ __half g_WuH[(size_t)K_EMB * K_INDIM];     // W_u^T [N][K] fp16
__device__ __half g_WtH[(size_t)K_MM * K_EMB];        // W_t^T [N][K] fp16
__device__ __half g_latent[(size_t)K_ROWS * K_EMB];   // fp16
__device__ float  g_flatm[(size_t)K_ROWS * K_MM];     // fp32 (expm input)
__device__ __half g_fexpP[(size_t)K_ROWS * K_PACK];   // packed strict-upper expm
__device__ __half g_WsPH[(size_t)K_OUTDIM * K_PACK];  // packed W_s^T [N][Kp] fp16
__device__ float  g_bias2[K_OUTDIM];                  // b_s + sum(diag rows W_s)

// ---------------- helpers ---------------------------------------------------
#define SWZ(x) ((x) ^ (((x) >> 3) & 0x70))

__device__ __forceinline__ void cpa16(uint32_t sdst, const void* g) {
    asm volatile("cp.async.cg.shared.global [%0], [%1], 16;\n" :: "r"(sdst), "l"(g));
}
__device__ __forceinline__ uint32_t smem_u32(const void* p) {
    return (uint32_t)__cvta_generic_to_shared(p);
}
__device__ __forceinline__ void ldsm4(uint32_t& r0, uint32_t& r1, uint32_t& r2,
                                      uint32_t& r3, uint32_t addr) {
    asm volatile("ldmatrix.sync.aligned.m8n8.x4.shared.b16 {%0,%1,%2,%3}, [%4];"
                 : "=r"(r0), "=r"(r1), "=r"(r2), "=r"(r3) : "r"(addr));
}
__device__ __forceinline__ void mma_f16(float* c, const uint32_t* a, const uint32_t* b) {
    asm volatile(
        "mma.sync.aligned.m16n8k16.row.col.f32.f16.f16.f32 "
        "{%0,%1,%2,%3}, {%4,%5,%6,%7}, {%8,%9}, {%0,%1,%2,%3};\n"
        : "+f"(c[0]), "+f"(c[1]), "+f"(c[2]), "+f"(c[3])
        : "r"(a[0]), "r"(a[1]), "r"(a[2]), "r"(a[3]), "r"(b[0]), "r"(b[1]));
}

// ---------------------------------------------------------------------------
// rms: scale row by rsqrt(mean(x^2)+eps), write fp16
// ---------------------------------------------------------------------------
__global__ void __launch_bounds__(256) rms_kernel(const float* __restrict__ x) {
    int row = blockIdx.x;
    const float4* xr = reinterpret_cast<const float4*>(x + (size_t)row * K_INDIM);
    float s = 0.f;
#pragma unroll 4
    for (int i = threadIdx.x; i < K_INDIM / 4; i += 256) {
        float4 v = xr[i];
        s += v.x * v.x + v.y * v.y + v.z * v.z + v.w * v.w;
    }
#pragma unroll
    for (int o = 16; o; o >>= 1) s += __shfl_xor_sync(0xFFFFFFFFu, s, o);
    __shared__ float ws[8];
    __shared__ float ssc;
    if ((threadIdx.x & 31) == 0) ws[threadIdx.x >> 5] = s;
    __syncthreads();
    if (threadIdx.x == 0) {
        float t = 0.f;
#pragma unroll
        for (int i = 0; i < 8; i++) t += ws[i];
        ssc = rsqrtf(t * (1.0f / K_INDIM) + RMS_EPS);
    }
    __syncthreads();
    float sc = ssc;
    __half2* o = reinterpret_cast<__half2*>(g_xh + (size_t)row * K_INDIM);
#pragma unroll 4
    for (int i = threadIdx.x; i < K_INDIM / 4; i += 256) {
        float4 v = xr[i];
        o[2 * i]     = __floats2half2_rn(v.x * sc, v.y * sc);
        o[2 * i + 1] = __floats2half2_rn(v.z * sc, v.w * sc);
    }
}

// ---------------------------------------------------------------------------
// transpose fp32 [K][N] -> fp16 [N][K].  SEL 0 -> g_WuH, 1 -> g_WtH
// ---------------------------------------------------------------------------
template <int SEL>
__global__ void __launch_bounds__(256) transpose_h(const float* __restrict__ in, int K, int N) {
    __half* out = (SEL == 0) ? g_WuH : g_WtH;
    __shared__ float t[32][33];
    int bx = blockIdx.x * 32;   // over N
    int by = blockIdx.y * 32;   // over K
    int tx = threadIdx.x, ty = threadIdx.y;
#pragma unroll
    for (int i = 0; i < 32; i += 8)
        t[ty + i][tx] = in[(size_t)(by + ty + i) * N + bx + tx];
    __syncthreads();
#pragma unroll
    for (int i = 0; i < 32; i += 8)
        out[(size_t)(bx + ty + i) * K + by + tx] = __float2half_rn(t[tx][ty + i]);
}

// ---------------------------------------------------------------------------
// pack W_s^T: g_WsPH[n][q] = Ws[p(q)][n] for the 120 strictly-upper positions
// ---------------------------------------------------------------------------
__global__ void __launch_bounds__(256) pack_ws_h(const float* __restrict__ Ws) {
    __shared__ float t[32][33];
    int qt = blockIdx.x * 32, nt = blockIdx.y * 32;
    int tx = threadIdx.x, ty = threadIdx.y;
#pragma unroll
    for (int i = 0; i < 32; i += 8) {
        int q = qt + ty + i;
        float v = 0.f;
        if (q < 120) {
            int ii = 0, rem = q;
            while (rem >= 15 - ii) { rem -= 15 - ii; ii++; }
            int p = ii * 16 + ii + 1 + rem;
            v = Ws[(size_t)p * K_OUTDIM + nt + tx];
        }
        t[ty + i][tx] = v;
    }
    __syncthreads();
#pragma unroll
    for (int i = 0; i < 32; i += 8)
        g_WsPH[(size_t)(nt + ty + i) * K_PACK + qt + tx] = __float2half_rn(t[tx][ty + i]);
}

__global__ void __launch_bounds__(256) bias2_kernel(const float* __restrict__ Ws,
                                                    const float* __restrict__ bs) {
    int n = blockIdx.x * 256 + threadIdx.x;
    float s = bs[n];
#pragma unroll
    for (int d = 0; d < 16; d++) s += Ws[(size_t)(17 * d) * K_OUTDIM + n];
    g_bias2[n] = s;
}

// ---------------------------------------------------------------------------
// fp16 mma.sync GEMM: CTA 128(M)x256(N), K-tile 64, 4-stage cp.async,
// 8 warps = 2(M) x 4(N), warp tile 64x64, ldmatrix fragment loads.
// MODE 0: g_xh    @ g_WuH  + b_u   -> g_latent (fp16)
// MODE 1: g_latent@ g_WtH  + b_t   -> g_flatm  (fp32, strict-upper mask)
// MODE 2: g_fexpP @ g_WsPH + bias2 -> Cout     (fp32)
// ---------------------------------------------------------------------------
#define BM 128
#define BN 256
#define BK 64
#define STAGE_B ((BM * BK + BN * BK) * 2)     // 49152 bytes
#define A_BYTES (BM * BK * 2)                 // 16384
#define SMEM_GEMM (4 * STAGE_B)               // 196608

template <int MODE>
__global__ void __launch_bounds__(256, 1) gemm_h(const float* __restrict__ bias_in,
                                                 float* __restrict__ Cout) {
    constexpr int KDIM = (MODE == 0) ? K_INDIM : (MODE == 1) ? K_EMB : K_PACK;
    constexpr int NDIM = (MODE == 0) ? K_EMB : (MODE == 1) ? K_MM : K_OUTDIM;
    constexpr int KT = KDIM / BK;

    const __half* __restrict__ A =
        (MODE == 0) ? g_xh : (MODE == 1) ? g_latent : g_fexpP;
    const __half* __restrict__ B =
        (MODE == 0) ? g_WuH : (MODE == 1) ? g_WtH : g_WsPH;
    const float* __restrict__ bias = (MODE == 2) ? g_bias2 : bias_in;

    extern __shared__ char smem[];
    const uint32_t sb = smem_u32(smem);
    const int tid = threadIdx.x, warp = tid >> 5, lane = tid & 31;
    const int bn = blockIdx.x * BN, bm = blockIdx.y * BM;
    const int wm = (warp >> 2) * 64, wn = (warp & 3) * 64;
    const int g = lane >> 2, t = lane & 3;

    // ldmatrix per-lane base offsets (swizzled); kk advances via XOR
    const uint32_t aoff =
        SWZ(((lane & 15) * 128) + ((lane >> 4) * 16)) + (uint32_t)wm * 128;
    const uint32_t boff =
        SWZ((((lane & 7) + ((lane >> 4) << 3)) * 128) + (((lane >> 3) & 1) * 16)) +
        (uint32_t)wn * 128;

    float acc[4][8][4];
#pragma unroll
    for (int mi = 0; mi < 4; mi++)
#pragma unroll
        for (int nj = 0; nj < 8; nj++)
#pragma unroll
            for (int r = 0; r < 4; r++) acc[mi][nj][r] = 0.f;

    auto load_tile = [&](int kt, int st) {
        uint32_t ab = sb + st * STAGE_B;
        uint32_t bb = ab + A_BYTES;
        const __half* Ag = A + (size_t)bm * KDIM + kt * BK;
#pragma unroll
        for (int i = 0; i < 4; i++) {
            int v = tid + i * 256, r = v >> 3, c = v & 7;
            cpa16(ab + SWZ(r * 128 + c * 16), Ag + (size_t)r * KDIM + c * 8);
        }
        const __half* Bg = B + (size_t)bn * KDIM + kt * BK;
#pragma unroll
        for (int i = 0; i < 8; i++) {
            int v = tid + i * 256, r = v >> 3, c = v & 7;
            cpa16(bb + SWZ(r * 128 + c * 16), Bg + (size_t)r * KDIM + c * 8);
        }
        asm volatile("cp.async.commit_group;\n" ::: "memory");
    };

    auto compute = [&](int st) {
        uint32_t ab = sb + st * STAGE_B;
        uint32_t bb = ab + A_BYTES;
#pragma unroll
        for (int kk = 0; kk < BK; kk += 16) {
            uint32_t a[4][4], b[4][4];
#pragma unroll
            for (int mi = 0; mi < 4; mi++)
                ldsm4(a[mi][0], a[mi][1], a[mi][2], a[mi][3],
                      ab + ((aoff ^ (kk * 2)) + mi * 2048));
#pragma unroll
            for (int fj = 0; fj < 4; fj++)
                ldsm4(b[fj][0], b[fj][1], b[fj][2], b[fj][3],
                      bb + ((boff ^ (kk * 2)) + fj * 2048));
#pragma unroll
            for (int mi = 0; mi < 4; mi++)
#pragma unroll
                for (int fj = 0; fj < 4; fj++) {
                    mma_f16(acc[mi][2 * fj],     a[mi], &b[fj][0]);
                    mma_f16(acc[mi][2 * fj + 1], a[mi], &b[fj][2]);
                }
        }
    };

    // prefetch up to 3 tiles
    if (0 < KT) load_tile(0, 0);
    if (1 < KT) load_tile(1, 1);
    if (2 < KT) load_tile(2, 2);

    for (int kt = 0; kt < KT; kt++) {
        int rem = KT - 1 - kt;
        if (rem >= 2)      asm volatile("cp.async.wait_group 2;\n" ::: "memory");
        else if (rem == 1) asm volatile("cp.async.wait_group 1;\n" ::: "memory");
        else               asm volatile("cp.async.wait_group 0;\n" ::: "memory");
        __syncthreads();
        if (kt + 3 < KT) load_tile(kt + 3, (kt + 3) & 3);
        compute(kt & 3);
    }

    // epilogue
#pragma unroll
    for (int mi = 0; mi < 4; mi++) {
        int r0 = bm + wm + mi * 16 + g;
#pragma unroll
        for (int nj = 0; nj < 8; nj++) {
            int col = bn + wn + nj * 8 + 2 * t;
            float b0 = bias[col], b1 = bias[col + 1];
            float v00 = acc[mi][nj][0] + b0;
            float v01 = acc[mi][nj][1] + b1;
            float v10 = acc[mi][nj][2] + b0;
            float v11 = acc[mi][nj][3] + b1;
            if (MODE == 0) {
                *reinterpret_cast<__half2*>(&g_latent[(size_t)r0 * NDIM + col]) =
                    __floats2half2_rn(v00, v01);
                *reinterpret_cast<__half2*>(&g_latent[(size_t)(r0 + 8) * NDIM + col]) =
                    __floats2half2_rn(v10, v11);
            } else if (MODE == 1) {
                if (!((col & 15) > (col >> 4)))             { v00 = 0.f; v10 = 0.f; }
                if (!(((col + 1) & 15) > ((col + 1) >> 4))) { v01 = 0.f; v11 = 0.f; }
                *reinterpret_cast<float2*>(&g_flatm[(size_t)r0 * NDIM + col]) =
                    make_float2(v00, v01);
                *reinterpret_cast<float2*>(&g_flatm[(size_t)(r0 + 8) * NDIM + col]) =
                    make_float2(v10, v11);
            } else {
                *reinterpret_cast<float2*>(&Cout[(size_t)r0 * NDIM + col]) =
                    make_float2(v00, v01);
                *reinterpret_cast<float2*>(&Cout[(size_t)(r0 + 8) * NDIM + col]) =
                    make_float2(v10, v11);
            }
        }
    }
}

// ---------------------------------------------------------------------------
// expm of strictly-upper 16x16 via Taylor (exact: M^16 = 0), packed fp16 out
// ---------------------------------------------------------------------------
__global__ void __launch_bounds__(256) expm_kernel() {
    int row = blockIdx.x;
    int idx = threadIdx.x;
    int i = idx >> 4, j = idx & 15;

    __shared__ float Msm[256];
    __shared__ float Ts[256];

    float m = g_flatm[(size_t)row * K_MM + idx];
    Msm[idx] = m;
    Ts[idx] = m;
    float res = ((i == j) ? 1.0f : 0.0f) + m;
    __syncthreads();

#pragma unroll
    for (int k = 2; k <= 15; k++) {
        float s = 0.f;
        if (j - i >= k) {
#pragma unroll
            for (int l = 0; l < 16; l++) s += Ts[i * 16 + l] * Msm[l * 16 + j];
            s /= (float)k;
        }
        __syncthreads();
        Ts[idx] = s;
        res += s;
        __syncthreads();
    }
    if (j > i) {
        int q = i * 15 - (i * (i - 1)) / 2 + (j - i - 1);
        g_fexpP[(size_t)row * K_PACK + q] = __float2half_rn(res);
    }
    if (idx < 8) g_fexpP[(size_t)row * K_PACK + 120 + idx] = __half(0.f);
}

// ---------------------------------------------------------------------------
// launch
// ---------------------------------------------------------------------------
extern "C" void kernel_launch(void* const* d_in, const int* in_sizes, int n_in,
                              void* d_out, int out_size) {
    (void)in_sizes; (void)n_in; (void)out_size;
    const float* x   = (const float*)d_in[0];
    const float* W_u = (const float*)d_in[1];
    const float* b_u = (const float*)d_in[2];
    const float* W_t = (const float*)d_in[3];
    const float* b_t = (const float*)d_in[4];
    const float* W_s = (const float*)d_in[5];
    const float* b_s = (const float*)d_in[6];
    float* out = (float*)d_out;

    cudaFuncSetAttribute(gemm_h<0>, cudaFuncAttributeMaxDynamicSharedMemorySize, SMEM_GEMM);
    cudaFuncSetAttribute(gemm_h<1>, cudaFuncAttributeMaxDynamicSharedMemorySize, SMEM_GEMM);
    cudaFuncSetAttribute(gemm_h<2>, cudaFuncAttributeMaxDynamicSharedMemorySize, SMEM_GEMM);

    rms_kernel<<<K_ROWS, 256>>>(x);
    transpose_h<0><<<dim3(K_EMB / 32, K_INDIM / 32), dim3(32, 8)>>>(W_u, K_INDIM, K_EMB);
    transpose_h<1><<<dim3(K_MM / 32, K_EMB / 32), dim3(32, 8)>>>(W_t, K_EMB, K_MM);
    pack_ws_h<<<dim3(K_PACK / 32, K_OUTDIM / 32), dim3(32, 8)>>>(W_s);
    bias2_kernel<<<K_OUTDIM / 256, 256>>>(W_s, b_s);

    // GEMM1: latent = xh @ WuT + b_u           [8192 x 1024], K=4096
    gemm_h<0><<<dim3(K_EMB / BN, K_ROWS / BM), 256, SMEM_GEMM>>>(b_u, nullptr);

    // GEMM2: flatm = latent @ WtT + b_t, mask  [8192 x 256], K=1024
    gemm_h<1><<<dim3(K_MM / BN, K_ROWS / BM), 256, SMEM_GEMM>>>(b_t, nullptr);

    // expm -> packed fp16
    expm_kernel<<<K_ROWS, 256>>>();

    // GEMM3: out = fexpP @ WsPT + bias2        [8192 x 4096], K=128
    gemm_h<2><<<dim3(K_OUTDIM / BN, K_ROWS / BM), 256, SMEM_GEMM>>>(nullptr, out);
}